// round 15
// baseline (speedup 1.0000x reference)
#include <cuda_runtime.h>
#include <cuda_bf16.h>
#include <cstdint>

// TorchBSplineBasis: out[b, i*10+j] = A_b[i] * B_b[j], cubic B-spline bases
// (NUM_BASIS=10, DEGREE=3, 14 knots/dim) of t[b,0], t[b,1].
//
// R14 (resubmit; previous bench was a broker-capacity timeout):
// stage ONLY the bases (A,B: 20 floats/row, pad-12 rows) in SMEM, then a
// store phase where thread e<100 owns output column e with compile-time
// (i=e/10, j=e%10): loop over the CTA's 128 rows doing 2 conflict-free LDS +
// FMUL + coalesced STG.32. SMEM drops 51.2KB -> ~12KB, lifting the occupancy
// ceiling from 16 to 64 warps/SM (the invariant that pinned R3/R6/R7/R12 at
// ~33us). No TMA: LTS cap is path-independent (STG == TMA).

#define ROWS_PER_BLOCK 128
#define NB 10
#define NKNOT 14
#define NPAIRS 33           // 12 (k=1) + 11 (k=2) + 10 (k=3)
#define ROW_FLOATS 100
#define PAD 12              // 48B row stride: 16B-aligned rows, conflict-free phases

__global__ __launch_bounds__(ROWS_PER_BLOCK)
void bspline_basis_kernel(const float* __restrict__ t,
                          const float* __restrict__ knots,
                          float* __restrict__ out,
                          int rows)
{
    __shared__ float sA[ROWS_PER_BLOCK][PAD];
    __shared__ float sB[ROWS_PER_BLOCK][PAD];
    __shared__ float s_kn[2][NKNOT];
    __shared__ float s_inv1[2][NPAIRS];
    __shared__ float s_inv2[2][NPAIRS];

    const int tid = threadIdx.x;

    if (tid < 2 * NKNOT) {
        s_kn[tid / NKNOT][tid % NKNOT] = knots[tid];
    }
    __syncthreads();

    // reciprocal tables, matching jnp.where(d==0, 0, 1/d)
    if (tid < 2 * NPAIRS) {
        int d = tid / NPAIRS;
        int p = tid % NPAIRS;
        int k, i;
        if (p < 12)      { k = 1; i = p; }
        else if (p < 23) { k = 2; i = p - 12; }
        else             { k = 3; i = p - 23; }
        float d1 = s_kn[d][i + k]     - s_kn[d][i];
        float d2 = s_kn[d][i + k + 1] - s_kn[d][i + 1];
        s_inv1[d][p] = (d1 == 0.0f) ? 0.0f : 1.0f / d1;
        s_inv2[d][p] = (d2 == 0.0f) ? 0.0f : 1.0f / d2;
    }
    __syncthreads();

    const int row0 = blockIdx.x * ROWS_PER_BLOCK;
    const int row  = row0 + tid;

    // ---- zero this thread's base rows (16B-aligned: PAD=12 -> 48B stride) ----
    {
        const float4 z4 = make_float4(0.f, 0.f, 0.f, 0.f);
        *reinterpret_cast<float4*>(&sA[tid][0]) = z4;
        *reinterpret_cast<float4*>(&sA[tid][4]) = z4;
        *reinterpret_cast<float2*>(&sA[tid][8]) = make_float2(0.f, 0.f);
        *reinterpret_cast<float4*>(&sB[tid][0]) = z4;
        *reinterpret_cast<float4*>(&sB[tid][4]) = z4;
        *reinterpret_cast<float2*>(&sB[tid][8]) = make_float2(0.f, 0.f);
    }

    if (row < rows) {
        const float2 tv = *reinterpret_cast<const float2*>(t + (size_t)row * 2);
        const float tt[2] = { tv.x, tv.y };

        #pragma unroll
        for (int d = 0; d < 2; d++) {
            const float tc = tt[d];

            // knot span: j = #{i in [1,13] : t >= kn[i]}  =>  kn[j] <= t < kn[j+1]
            int j = 0;
            #pragma unroll
            for (int i = 1; i < NKNOT; i++) j += (tc >= s_kn[d][i]) ? 1 : 0;
            const bool valid = (tc >= s_kn[d][0]) && (j < NKNOT - 1);

            // windowed Cox-de Boor: val[m] = B[j-k+m]^(k) for m = 0..k
            float val[4];
            val[0] = valid ? 1.0f : 0.0f;
            val[1] = val[2] = val[3] = 0.0f;

            int base = 0;
            #pragma unroll
            for (int k = 1; k <= 3; k++) {
                const int msz = 13 - k;            // table length at this level
                float nxt[4];
                #pragma unroll
                for (int m = 0; m <= k; m++) {
                    const int  i  = j - k + m;
                    const bool ok = ((unsigned)i < (unsigned)msz);
                    const int  ic = ok ? i : 0;
                    const float left  = (m > 0) ? val[m - 1] : 0.0f;
                    const float right = (m < k) ? val[m]     : 0.0f;
                    const float w1 = (tc - s_kn[d][ic])         * s_inv1[d][base + ic];
                    const float w2 = (s_kn[d][ic + k + 1] - tc) * s_inv2[d][base + ic];
                    nxt[m] = ok ? (w1 * left + w2 * right) : 0.0f;
                }
                #pragma unroll
                for (int m = 0; m <= k; m++) val[m] = nxt[m];
                base += msz;
            }

            // scatter the (at most) 4 nonzero basis values into the dense row
            float* srow = (d == 0) ? sA[tid] : sB[tid];
            #pragma unroll
            for (int m = 0; m < 4; m++) {
                const int ib = j - 3 + m;
                if ((unsigned)ib < (unsigned)NB) srow[ib] = val[m];
            }
        }
    }
    __syncthreads();

    // ---- store phase: thread e<100 owns column e; i,j are compile-time-fixed
    //      per thread; loop over rows with coalesced STG.32 (400B/row). ----
    if (tid < ROW_FLOATS) {
        const int i = tid / NB;          // constant per thread
        const int j = tid - i * NB;      // constant per thread
        const int rlim = min(ROWS_PER_BLOCK, rows - row0);
        float* op = out + (size_t)row0 * ROW_FLOATS + tid;

        int r = 0;
        #pragma unroll 4
        for (; r + 4 <= rlim; r += 4) {
            const float p0 = sA[r    ][i] * sB[r    ][j];
            const float p1 = sA[r + 1][i] * sB[r + 1][j];
            const float p2 = sA[r + 2][i] * sB[r + 2][j];
            const float p3 = sA[r + 3][i] * sB[r + 3][j];
            op[(size_t)(r    ) * ROW_FLOATS] = p0;
            op[(size_t)(r + 1) * ROW_FLOATS] = p1;
            op[(size_t)(r + 2) * ROW_FLOATS] = p2;
            op[(size_t)(r + 3) * ROW_FLOATS] = p3;
        }
        for (; r < rlim; r++) {
            op[(size_t)r * ROW_FLOATS] = sA[r][i] * sB[r][j];
        }
    }
}

extern "C" void kernel_launch(void* const* d_in, const int* in_sizes, int n_in,
                              void* d_out, int out_size) {
    const float* t     = (const float*)d_in[0];   // (BATCH, 2) fp32
    const float* knots = (const float*)d_in[1];   // (2, 14) fp32
    float* out = (float*)d_out;                   // (BATCH, 100) fp32

    const int rows = in_sizes[0] / 2;
    const int grid = (rows + ROWS_PER_BLOCK - 1) / ROWS_PER_BLOCK;

    bspline_basis_kernel<<<grid, ROWS_PER_BLOCK>>>(t, knots, out, rows);
}

// round 16
// speedup vs baseline: 1.0255x; 1.0255x over previous
#include <cuda_runtime.h>
#include <cuda_bf16.h>
#include <cstdint>

// TorchBSplineBasis: out[b, i*10+j] = A_b[i] * B_b[j], cubic B-spline bases
// (NUM_BASIS=10, DEGREE=3, 14 knots/dim) of t[b,0], t[b,1].
//
// R16: exact R6 shell (sparse 4-wide de Boor, zeroed gmem-layout SMEM tile,
// 16-product scatter, one cp.async.bulk per CTA) with ROWS_PER_BLOCK=112:
// 44.8KB SMEM -> 5 CTAs/SM (224KB of 228KB) = 20 warp slots + 5 independent
// TMA drain streams per SM (vs 16 + 4 at 128 rows). The store path's L1 cost
// per byte (the R14 failure mode) is unchanged.

#define ROWS_PER_BLOCK 112
#define NB 10
#define NKNOT 14
#define NPAIRS 33           // 12 (k=1) + 11 (k=2) + 10 (k=3)
#define ROW_FLOATS 100
#define SMEM_PROD_BYTES (ROWS_PER_BLOCK * ROW_FLOATS * 4)   // 44800

__device__ __forceinline__ uint32_t smem_u32(const void* p) {
    uint32_t a;
    asm("{ .reg .u64 t; cvta.to.shared.u64 t, %1; cvt.u32.u64 %0, t; }"
        : "=r"(a) : "l"(p));
    return a;
}

__global__ __launch_bounds__(ROWS_PER_BLOCK)
void bspline_basis_kernel(const float* __restrict__ t,
                          const float* __restrict__ knots,
                          float* __restrict__ out,
                          int rows)
{
    extern __shared__ float s_prod[];          // [112][100], gmem layout
    __shared__ float s_kn[2][NKNOT];
    __shared__ float s_inv1[2][NPAIRS];
    __shared__ float s_inv2[2][NPAIRS];

    const int tid = threadIdx.x;

    if (tid < 2 * NKNOT) {
        s_kn[tid / NKNOT][tid % NKNOT] = knots[tid];
    }
    __syncthreads();

    // reciprocal tables, matching jnp.where(d==0, 0, 1/d)
    if (tid < 2 * NPAIRS) {
        int d = tid / NPAIRS;
        int p = tid % NPAIRS;
        int k, i;
        if (p < 12)      { k = 1; i = p; }
        else if (p < 23) { k = 2; i = p - 12; }
        else             { k = 3; i = p - 23; }
        float d1 = s_kn[d][i + k]     - s_kn[d][i];
        float d2 = s_kn[d][i + k + 1] - s_kn[d][i + 1];
        s_inv1[d][p] = (d1 == 0.0f) ? 0.0f : 1.0f / d1;
        s_inv2[d][p] = (d2 == 0.0f) ? 0.0f : 1.0f / d2;
    }
    __syncthreads();

    const int row0 = blockIdx.x * ROWS_PER_BLOCK;
    const int row  = row0 + tid;
    float* const dst = s_prod + tid * ROW_FLOATS;

    // zero this thread's SMEM row (25 independent STS.128)
    const float4 z4 = make_float4(0.f, 0.f, 0.f, 0.f);
    #pragma unroll
    for (int e = 0; e < ROW_FLOATS; e += 4) {
        *reinterpret_cast<float4*>(dst + e) = z4;
    }

    if (row < rows) {
        const float2 tv = *reinterpret_cast<const float2*>(t + (size_t)row * 2);
        const float tt[2] = { tv.x, tv.y };

        float vA[4], vB[4];
        int   jA = 0, jB = 0;

        #pragma unroll
        for (int d = 0; d < 2; d++) {
            const float tc = tt[d];

            // knot span: j = #{i in [1,13] : t >= kn[i]}  =>  kn[j] <= t < kn[j+1]
            int j = 0;
            #pragma unroll
            for (int i = 1; i < NKNOT; i++) j += (tc >= s_kn[d][i]) ? 1 : 0;
            const bool valid = (tc >= s_kn[d][0]) && (j < NKNOT - 1);

            // windowed Cox-de Boor: val[m] = B[j-k+m]^(k) for m = 0..k
            float val[4];
            val[0] = valid ? 1.0f : 0.0f;
            val[1] = val[2] = val[3] = 0.0f;

            int base = 0;
            #pragma unroll
            for (int k = 1; k <= 3; k++) {
                const int msz = 13 - k;            // table length at this level
                float nxt[4];
                #pragma unroll
                for (int m = 0; m <= k; m++) {
                    const int  i  = j - k + m;
                    const bool ok = ((unsigned)i < (unsigned)msz);
                    const int  ic = ok ? i : 0;
                    const float left  = (m > 0) ? val[m - 1] : 0.0f;
                    const float right = (m < k) ? val[m]     : 0.0f;
                    const float w1 = (tc - s_kn[d][ic])         * s_inv1[d][base + ic];
                    const float w2 = (s_kn[d][ic + k + 1] - tc) * s_inv2[d][base + ic];
                    nxt[m] = ok ? (w1 * left + w2 * right) : 0.0f;
                }
                #pragma unroll
                for (int m = 0; m <= k; m++) val[m] = nxt[m];
                base += msz;
            }

            if (d == 0) {
                jA = j;
                #pragma unroll
                for (int m = 0; m < 4; m++) vA[m] = val[m];
            } else {
                jB = j;
                #pragma unroll
                for (int m = 0; m < 4; m++) vB[m] = val[m];
            }
        }

        // scatter the 16 nonzero products: basis indices jA-3..jA x jB-3..jB
        #pragma unroll
        for (int a = 0; a < 4; a++) {
            const int ia = jA - 3 + a;
            if ((unsigned)ia < (unsigned)NB) {
                #pragma unroll
                for (int b = 0; b < 4; b++) {
                    const int ib = jB - 3 + b;
                    if ((unsigned)ib < (unsigned)NB) {
                        dst[ia * NB + ib] = vA[a] * vB[b];
                    }
                }
            }
        }
    }
    __syncthreads();

    // one TMA bulk store: SMEM image is byte-identical to the gmem destination
    if (tid == 0) {
        const int tileRows = min(ROWS_PER_BLOCK, rows - row0);
        const uint32_t bytes = (uint32_t)tileRows * (ROW_FLOATS * 4);
        const uint32_t saddr = smem_u32(s_prod);
        const uint64_t gaddr = (uint64_t)(uintptr_t)(out + (size_t)row0 * ROW_FLOATS);

        asm volatile("fence.proxy.async.shared::cta;" ::: "memory");
        asm volatile("cp.async.bulk.global.shared::cta.bulk_group [%0], [%1], %2;"
                     :: "l"(gaddr), "r"(saddr), "r"(bytes) : "memory");
        asm volatile("cp.async.bulk.commit_group;" ::: "memory");
        asm volatile("cp.async.bulk.wait_group.read 0;" ::: "memory");
    }
}

extern "C" void kernel_launch(void* const* d_in, const int* in_sizes, int n_in,
                              void* d_out, int out_size) {
    const float* t     = (const float*)d_in[0];   // (BATCH, 2) fp32
    const float* knots = (const float*)d_in[1];   // (2, 14) fp32
    float* out = (float*)d_out;                   // (BATCH, 100) fp32

    const int rows = in_sizes[0] / 2;
    const int grid = (rows + ROWS_PER_BLOCK - 1) / ROWS_PER_BLOCK;

    static bool attr_set = false;   // idempotent host-side attribute, not a work guard
    if (!attr_set) {
        cudaFuncSetAttribute(bspline_basis_kernel,
                             cudaFuncAttributeMaxDynamicSharedMemorySize,
                             SMEM_PROD_BYTES);
        attr_set = true;
    }

    bspline_basis_kernel<<<grid, ROWS_PER_BLOCK, SMEM_PROD_BYTES>>>(t, knots, out, rows);
}